// round 14
// baseline (speedup 1.0000x reference)
#include <cuda_runtime.h>
#include <cuda_fp16.h>

#define NBATCH 4
#define CCH 256
#define FH 100
#define FW 152
#define HW (FH*FW)           // 15200
#define FWC (FW*CCH)         // 38912  (element stride)
#define NROI 4000
#define OUT_PER_ROI (CCH*49)       // 12544 floats, linear
#define SMEM_BYTES (OUT_PER_ROI*2) // 25088 B (fp16 stage)

// NHWC scratch in fp16 (31MB). Math stays fp32; storage is half.
__device__ __half g_nhwc_h[NBATCH * HW * CCH];

// ---------------------------------------------------------------------------
// Kernel A: NCHW(f32) -> NHWC(fp16) transpose. 128ch x 32hw tiles, 3800
// blocks, 16 independent LDGs/thread. ~13us measured (near DRAM floor).
// ---------------------------------------------------------------------------
__global__ __launch_bounds__(256) void transpose_kernel(const float* __restrict__ in) {
    __shared__ float tile[128][33];
    const int b   = blockIdx.z;
    const int hw0 = blockIdx.x * 32;
    const int c0  = blockIdx.y * 128;
    const int x   = threadIdx.x;
    const int y   = threadIdx.y;

    const float* src = in + (size_t)b * CCH * HW + (size_t)(c0 + y) * HW + hw0 + x;
    #pragma unroll
    for (int k = 0; k < 16; k++)
        tile[y + 8*k][x] = __ldcs(src + (size_t)(8*k) * HW);
    __syncthreads();

    __half* dst = g_nhwc_h + (size_t)b * HW * CCH + (size_t)hw0 * CCH + c0 + x;
    #pragma unroll
    for (int k = 0; k < 4; k++) {
        const int hw = y + 8*k;
        #pragma unroll
        for (int m = 0; m < 4; m++)
            dst[(size_t)hw * CCH + 32*m] = __float2half_rn(tile[x + 32*m][hw]);
    }
}

// ---------------------------------------------------------------------------
// Row-group body: half2 gathers, 4-weight dot product per sample (weights
// from the per-roi LUT with mask and 0.25 pool factor folded in), pair-sum
// rolling carry, fp16 smem stage.
// ---------------------------------------------------------------------------
template<int NR>
__device__ __forceinline__ void process_rows_h2(
    int i0, const __half* __restrict__ fbase, int c0,
    const int* s_ws, const int* s_hs,
    const float (*s_w4)[8][4],
    __half* s_out)
{
    float2 hprev[7];
    #pragma unroll
    for (int k = 0; k < NR; ++k) {
        const int i = i0 + k;
        const __half* r0 = fbase + s_hs[i] * FWC;
        const float (*wrow)[4] = s_w4[i];

        float2 cur[8];
        #pragma unroll
        for (int j = 0; j < 8; j++) {
            const int w0 = s_ws[j];
            float2 a00 = __half22float2(*(const half2*)(r0 + w0));
            float2 a01 = __half22float2(*(const half2*)(r0 + w0 + CCH));
            float2 a10 = __half22float2(*(const half2*)(r0 + w0 + FWC));
            float2 a11 = __half22float2(*(const half2*)(r0 + w0 + FWC + CCH));
            float q0 = wrow[j][0], q1 = wrow[j][1];
            float q2 = wrow[j][2], q3 = wrow[j][3];
            cur[j].x = fmaf(a11.x, q3, fmaf(a10.x, q2, fmaf(a01.x, q1, a00.x * q0)));
            cur[j].y = fmaf(a11.y, q3, fmaf(a10.y, q2, fmaf(a01.y, q1, a00.y * q0)));
        }

        float2 hcur[7];
        #pragma unroll
        for (int j = 0; j < 7; j++) {
            hcur[j].x = cur[j].x + cur[j+1].x;
            hcur[j].y = cur[j].y + cur[j+1].y;
        }

        if (k > 0) {
            int rb = (i - 1) * 7;
            #pragma unroll
            for (int j = 0; j < 7; j++) {
                // 0.25 already folded into the weights
                s_out[c0 * 49 + rb + j]       = __float2half_rn(hprev[j].x + hcur[j].x);
                s_out[(c0 + 1) * 49 + rb + j] = __float2half_rn(hprev[j].y + hcur[j].y);
            }
        }
        #pragma unroll
        for (int j = 0; j < 7; j++) hprev[j] = hcur[j];
    }
}

// ---------------------------------------------------------------------------
// Kernel B: one 256-thread block per roi. 128 half2-threads x 2 row-groups,
// proven 5+4 split, fp16 smem stage, per-roi 4-weight LUT.
// ONLY change vs round 13: launch_bounds(256,6) -> 42-reg target -> 6 CTAs
// = 48 warps/SM. Retrying the 6-CTA tier now that the LUT removed ~16 live
// registers from the mainloop (round 12's spill was with the old lerp code).
// Failure signature to watch: DRAM% > 33 means it spilled again -> revert.
// ---------------------------------------------------------------------------
__global__ __launch_bounds__(256, 6) void roi_kernel(
    const float* __restrict__ rois,
    const int*   __restrict__ bids,
    float*       __restrict__ out)
{
    extern __shared__ __half s_out[];   // [256][49] fp16
    __shared__ float s_w4[8][8][4];     // [i][j][w00,w01,w10,w11], 1KB
    __shared__ int   s_ws[8], s_hs[8];

    const int r = blockIdx.x;
    const int t = threadIdx.x;
    const int p = t & 127;             // channel-pair index (channels 2p, 2p+1)
    const int g = t >> 7;              // warps 0-3: g=0, warps 4-7: g=1

    if (t < 64) {
        const int i = t >> 3;          // h-sample index
        const int j = t & 7;           // w-sample index
        float x1 = rois[r*4 + 0] * 0.0625f;
        float x2 = rois[r*4 + 2] * 0.0625f;
        float y1 = rois[r*4 + 1] * 0.0625f;
        float y2 = rois[r*4 + 3] * 0.0625f;
        float bw = fmaxf(x2 - x1 + 1.0f, 0.0f) * (1.0f / 7.0f);
        float bh = fmaxf(y2 - y1 + 1.0f, 0.0f) * (1.0f / 7.0f);
        float w  = x1 + (float)j * bw;
        float h  = y1 + (float)i * bh;
        float wm = (w >= 0.0f && w < (float)FW) ? 1.0f : 0.0f;
        float hm = (h >= 0.0f && h < (float)FH) ? 1.0f : 0.0f;
        float wsf = fminf(fmaxf(floorf(w), 0.0f), (float)(FW - 2));
        float hsf = fminf(fmaxf(floorf(h), 0.0f), (float)(FH - 2));
        float wf = w - wsf;
        float hf = h - hsf;
        float m  = hm * wm * 0.25f;            // mask + pool factor folded
        s_w4[i][j][0] = (1.0f - hf) * (1.0f - wf) * m;
        s_w4[i][j][1] = (1.0f - hf) * wf * m;
        s_w4[i][j][2] = hf * (1.0f - wf) * m;
        s_w4[i][j][3] = hf * wf * m;
        if (i == 0) s_ws[j] = (int)wsf * CCH;  // pre-scaled column offset
        if (j == 0) s_hs[i] = (int)hsf;
    }
    __syncthreads();

    const int b = bids[r];
    const __half* fbase = g_nhwc_h + (size_t)b * HW * CCH + 2 * p;

    if (g == 0)
        process_rows_h2<5>(0, fbase, 2*p, s_ws, s_hs, s_w4, s_out);
    else
        process_rows_h2<4>(4, fbase, 2*p, s_ws, s_hs, s_w4, s_out);

    __syncthreads();

    // Coalesced flush: 4 halfs (8B-aligned) -> float4 store.
    float4* op = (float4*)(out + (size_t)r * OUT_PER_ROI);
    #pragma unroll
    for (int m = t; m < OUT_PER_ROI / 4; m += 256) {
        const half2* hp = (const half2*)(s_out + 4 * m);
        float2 lo = __half22float2(hp[0]);
        float2 hi = __half22float2(hp[1]);
        op[m] = make_float4(lo.x, lo.y, hi.x, hi.y);
    }
}

// ---------------------------------------------------------------------------
extern "C" void kernel_launch(void* const* d_in, const int* in_sizes, int n_in,
                              void* d_out, int out_size) {
    const float* features = (const float*)d_in[0];
    const float* rois     = (const float*)d_in[1];
    const int*   bids     = (const int*)d_in[2];
    float*       out      = (float*)d_out;

    dim3 tgrid(HW / 32, CCH / 128, NBATCH);   // (475, 2, 4) = 3800 blocks
    transpose_kernel<<<tgrid, dim3(32, 8)>>>(features);

    cudaFuncSetAttribute(roi_kernel,
                         cudaFuncAttributeMaxDynamicSharedMemorySize,
                         SMEM_BYTES);
    roi_kernel<<<NROI, 256, SMEM_BYTES>>>(rois, bids, out);
}

// round 16
// speedup vs baseline: 1.0866x; 1.0866x over previous
#include <cuda_runtime.h>
#include <cuda_fp16.h>

#define NBATCH 4
#define CCH 256
#define FH 100
#define FW 152
#define HW (FH*FW)           // 15200
#define FWC (FW*CCH)         // 38912  (element stride)
#define NROI 4000
#define OUT_PER_ROI (CCH*49)       // 12544 floats, linear
#define SMEM_BYTES (OUT_PER_ROI*2) // 25088 B (fp16 stage)

// NHWC scratch in fp16 (31MB). Math stays fp32; storage is half.
__device__ __half g_nhwc_h[NBATCH * HW * CCH];

// ---------------------------------------------------------------------------
// Kernel A: NCHW(f32) -> NHWC(fp16) transpose. 128ch x 32hw tiles.
// Write phase packs 2 consecutive channels per thread into one half2
// STG.32 -> 128B dense warp stores (was per-half STG.U16 = 64B/warp),
// 8 store instructions per thread instead of 16.
// ---------------------------------------------------------------------------
__global__ __launch_bounds__(256) void transpose_kernel(const float* __restrict__ in) {
    __shared__ float tile[128][33];
    const int b   = blockIdx.z;
    const int hw0 = blockIdx.x * 32;
    const int c0  = blockIdx.y * 128;
    const int x   = threadIdx.x;
    const int y   = threadIdx.y;

    const float* src = in + (size_t)b * CCH * HW + (size_t)(c0 + y) * HW + hw0 + x;
    #pragma unroll
    for (int k = 0; k < 16; k++)
        tile[y + 8*k][x] = __ldcs(src + (size_t)(8*k) * HW);
    __syncthreads();

    // Write phase: thread t handles channel-pair pi = t&63, hw rows t>>6 + 4k.
    const int t  = y * 32 + x;
    const int pi = t & 63;          // half2 index within the 128-ch tile
    const int h0 = t >> 6;          // 0..3
    __half2* dstb = (__half2*)(g_nhwc_h + (size_t)b * HW * CCH
                                        + (size_t)hw0 * CCH + c0);
    #pragma unroll
    for (int k = 0; k < 8; k++) {
        const int hw = h0 + 4 * k;  // covers 0..31
        float lo = tile[2*pi    ][hw];
        float hi = tile[2*pi + 1][hw];
        dstb[(size_t)hw * (CCH/2) + pi] = __floats2half2_rn(lo, hi);
    }
}

// ---------------------------------------------------------------------------
// Row-group body (round-13 verbatim): half2 gathers, 4-weight dot product
// per sample (weights from per-roi LUT, mask + 0.25 folded), pair-sum
// rolling carry, fp16 smem stage.
// ---------------------------------------------------------------------------
template<int NR>
__device__ __forceinline__ void process_rows_h2(
    int i0, const __half* __restrict__ fbase, int c0,
    const int* s_ws, const int* s_hs,
    const float (*s_w4)[8][4],
    __half* s_out)
{
    float2 hprev[7];
    #pragma unroll
    for (int k = 0; k < NR; ++k) {
        const int i = i0 + k;
        const __half* r0 = fbase + s_hs[i] * FWC;
        const float (*wrow)[4] = s_w4[i];

        float2 cur[8];
        #pragma unroll
        for (int j = 0; j < 8; j++) {
            const int w0 = s_ws[j];
            float2 a00 = __half22float2(*(const half2*)(r0 + w0));
            float2 a01 = __half22float2(*(const half2*)(r0 + w0 + CCH));
            float2 a10 = __half22float2(*(const half2*)(r0 + w0 + FWC));
            float2 a11 = __half22float2(*(const half2*)(r0 + w0 + FWC + CCH));
            float q0 = wrow[j][0], q1 = wrow[j][1];
            float q2 = wrow[j][2], q3 = wrow[j][3];
            cur[j].x = fmaf(a11.x, q3, fmaf(a10.x, q2, fmaf(a01.x, q1, a00.x * q0)));
            cur[j].y = fmaf(a11.y, q3, fmaf(a10.y, q2, fmaf(a01.y, q1, a00.y * q0)));
        }

        float2 hcur[7];
        #pragma unroll
        for (int j = 0; j < 7; j++) {
            hcur[j].x = cur[j].x + cur[j+1].x;
            hcur[j].y = cur[j].y + cur[j+1].y;
        }

        if (k > 0) {
            int rb = (i - 1) * 7;
            #pragma unroll
            for (int j = 0; j < 7; j++) {
                // 0.25 already folded into the weights
                s_out[c0 * 49 + rb + j]       = __float2half_rn(hprev[j].x + hcur[j].x);
                s_out[(c0 + 1) * 49 + rb + j] = __float2half_rn(hprev[j].y + hcur[j].y);
            }
        }
        #pragma unroll
        for (int j = 0; j < 7; j++) hprev[j] = hcur[j];
    }
}

// ---------------------------------------------------------------------------
// Kernel B (round-13 verbatim, 83.1us measured — the best configuration):
// one 256-thread block per roi, 128 half2-threads x 2 row-groups (5+4),
// fp16 smem stage, per-roi 4-weight LUT, (256,5) = 48 regs / 40 warps.
// The reg/occupancy axis is closed: 48 regs is the hard floor for this
// body (40-reg cap spills: R12, R14), 48x6 CTAs exceeds the regfile.
// ---------------------------------------------------------------------------
__global__ __launch_bounds__(256, 5) void roi_kernel(
    const float* __restrict__ rois,
    const int*   __restrict__ bids,
    float*       __restrict__ out)
{
    extern __shared__ __half s_out[];   // [256][49] fp16
    __shared__ float s_w4[8][8][4];     // [i][j][w00,w01,w10,w11], 1KB
    __shared__ int   s_ws[8], s_hs[8];

    const int r = blockIdx.x;
    const int t = threadIdx.x;
    const int p = t & 127;             // channel-pair index (channels 2p, 2p+1)
    const int g = t >> 7;              // warps 0-3: g=0, warps 4-7: g=1

    if (t < 64) {
        const int i = t >> 3;          // h-sample index
        const int j = t & 7;           // w-sample index
        float x1 = rois[r*4 + 0] * 0.0625f;
        float x2 = rois[r*4 + 2] * 0.0625f;
        float y1 = rois[r*4 + 1] * 0.0625f;
        float y2 = rois[r*4 + 3] * 0.0625f;
        float bw = fmaxf(x2 - x1 + 1.0f, 0.0f) * (1.0f / 7.0f);
        float bh = fmaxf(y2 - y1 + 1.0f, 0.0f) * (1.0f / 7.0f);
        float w  = x1 + (float)j * bw;
        float h  = y1 + (float)i * bh;
        float wm = (w >= 0.0f && w < (float)FW) ? 1.0f : 0.0f;
        float hm = (h >= 0.0f && h < (float)FH) ? 1.0f : 0.0f;
        float wsf = fminf(fmaxf(floorf(w), 0.0f), (float)(FW - 2));
        float hsf = fminf(fmaxf(floorf(h), 0.0f), (float)(FH - 2));
        float wf = w - wsf;
        float hf = h - hsf;
        float m  = hm * wm * 0.25f;            // mask + pool factor folded
        s_w4[i][j][0] = (1.0f - hf) * (1.0f - wf) * m;
        s_w4[i][j][1] = (1.0f - hf) * wf * m;
        s_w4[i][j][2] = hf * (1.0f - wf) * m;
        s_w4[i][j][3] = hf * wf * m;
        if (i == 0) s_ws[j] = (int)wsf * CCH;  // pre-scaled column offset
        if (j == 0) s_hs[i] = (int)hsf;
    }
    __syncthreads();

    const int b = bids[r];
    const __half* fbase = g_nhwc_h + (size_t)b * HW * CCH + 2 * p;

    if (g == 0)
        process_rows_h2<5>(0, fbase, 2*p, s_ws, s_hs, s_w4, s_out);
    else
        process_rows_h2<4>(4, fbase, 2*p, s_ws, s_hs, s_w4, s_out);

    __syncthreads();

    // Coalesced flush: 4 halfs (8B-aligned) -> float4 store.
    float4* op = (float4*)(out + (size_t)r * OUT_PER_ROI);
    #pragma unroll
    for (int m = t; m < OUT_PER_ROI / 4; m += 256) {
        const half2* hp = (const half2*)(s_out + 4 * m);
        float2 lo = __half22float2(hp[0]);
        float2 hi = __half22float2(hp[1]);
        op[m] = make_float4(lo.x, lo.y, hi.x, hi.y);
    }
}

// ---------------------------------------------------------------------------
extern "C" void kernel_launch(void* const* d_in, const int* in_sizes, int n_in,
                              void* d_out, int out_size) {
    const float* features = (const float*)d_in[0];
    const float* rois     = (const float*)d_in[1];
    const int*   bids     = (const int*)d_in[2];
    float*       out      = (float*)d_out;

    dim3 tgrid(HW / 32, CCH / 128, NBATCH);   // (475, 2, 4) = 3800 blocks
    transpose_kernel<<<tgrid, dim3(32, 8)>>>(features);

    cudaFuncSetAttribute(roi_kernel,
                         cudaFuncAttributeMaxDynamicSharedMemorySize,
                         SMEM_BYTES);
    roi_kernel<<<NROI, 256, SMEM_BYTES>>>(rois, bids, out);
}

// round 17
// speedup vs baseline: 1.1608x; 1.0683x over previous
#include <cuda_runtime.h>
#include <cuda_fp16.h>

#define NBATCH 4
#define CCH 256
#define FH 100
#define FW 152
#define HW (FH*FW)           // 15200
#define FWC (FW*CCH)         // 38912  (element stride)
#define NROI 4000
#define HALF_CH 128
#define OUT_PER_ROI (CCH*49)        // 12544 floats
#define HALF_OUT (HALF_CH*49)       // 6272 floats, linear region
#define SMEM_BYTES (HALF_OUT*2)     // 12544 B (fp16 stage)

// NHWC scratch in fp16 (31MB). Math stays fp32; storage is half.
__device__ __half g_nhwc_h[NBATCH * HW * CCH];

// ---------------------------------------------------------------------------
// Kernel A: NCHW(f32) -> NHWC(fp16) transpose. 128ch x 32hw tiles; write
// phase packs 2 channels per thread into one half2 STG.32 (dense 128B warp
// stores). ~13us measured (DRAM floor).
// ---------------------------------------------------------------------------
__global__ __launch_bounds__(256) void transpose_kernel(const float* __restrict__ in) {
    __shared__ float tile[128][33];
    const int b   = blockIdx.z;
    const int hw0 = blockIdx.x * 32;
    const int c0  = blockIdx.y * 128;
    const int x   = threadIdx.x;
    const int y   = threadIdx.y;

    const float* src = in + (size_t)b * CCH * HW + (size_t)(c0 + y) * HW + hw0 + x;
    #pragma unroll
    for (int k = 0; k < 16; k++)
        tile[y + 8*k][x] = __ldcs(src + (size_t)(8*k) * HW);
    __syncthreads();

    const int t  = y * 32 + x;
    const int pi = t & 63;
    const int h0 = t >> 6;
    __half2* dstb = (__half2*)(g_nhwc_h + (size_t)b * HW * CCH
                                        + (size_t)hw0 * CCH + c0);
    #pragma unroll
    for (int k = 0; k < 8; k++) {
        const int hw = h0 + 4 * k;
        float lo = tile[2*pi    ][hw];
        float hi = tile[2*pi + 1][hw];
        dstb[(size_t)hw * (CCH/2) + pi] = __floats2half2_rn(lo, hi);
    }
}

// ---------------------------------------------------------------------------
// Row-group body (round-13 math, unchanged): half2 gathers, 4-weight dot
// product per sample (per-roi LUT, mask + 0.25 folded), pair-sum rolling
// carry, fp16 smem stage.
// ---------------------------------------------------------------------------
template<int NR>
__device__ __forceinline__ void process_rows_h2(
    int i0, const __half* __restrict__ fbase, int c0,
    const int* s_ws, const int* s_hs,
    const float (*s_w4)[8][4],
    __half* s_out)
{
    float2 hprev[7];
    #pragma unroll
    for (int k = 0; k < NR; ++k) {
        const int i = i0 + k;
        const __half* r0 = fbase + s_hs[i] * FWC;
        const float (*wrow)[4] = s_w4[i];

        float2 cur[8];
        #pragma unroll
        for (int j = 0; j < 8; j++) {
            const int w0 = s_ws[j];
            float2 a00 = __half22float2(*(const half2*)(r0 + w0));
            float2 a01 = __half22float2(*(const half2*)(r0 + w0 + CCH));
            float2 a10 = __half22float2(*(const half2*)(r0 + w0 + FWC));
            float2 a11 = __half22float2(*(const half2*)(r0 + w0 + FWC + CCH));
            float q0 = wrow[j][0], q1 = wrow[j][1];
            float q2 = wrow[j][2], q3 = wrow[j][3];
            cur[j].x = fmaf(a11.x, q3, fmaf(a10.x, q2, fmaf(a01.x, q1, a00.x * q0)));
            cur[j].y = fmaf(a11.y, q3, fmaf(a10.y, q2, fmaf(a01.y, q1, a00.y * q0)));
        }

        float2 hcur[7];
        #pragma unroll
        for (int j = 0; j < 7; j++) {
            hcur[j].x = cur[j].x + cur[j+1].x;
            hcur[j].y = cur[j].y + cur[j+1].y;
        }

        if (k > 0) {
            int rb = (i - 1) * 7;
            #pragma unroll
            for (int j = 0; j < 7; j++) {
                // 0.25 already folded into the weights
                s_out[c0 * 49 + rb + j]       = __float2half_rn(hprev[j].x + hcur[j].x);
                s_out[(c0 + 1) * 49 + rb + j] = __float2half_rn(hprev[j].y + hcur[j].y);
            }
        }
        #pragma unroll
        for (int j = 0; j < 7; j++) hprev[j] = hcur[j];
    }
}

// ---------------------------------------------------------------------------
// Kernel B: ONE 128-THREAD BLOCK PER (roi, channel-half) — same per-thread
// work and memory pattern as round 16, but: 128-thread barriers (4 warps
// instead of 8), 10 CTAs/SM (reg-limited: 65536/(128*48)=10; smem 12.5KB*10
// =125KB ok) = same 40 warps at finer scheduling granularity and half the
// per-block tail. This is round-4's geometry without its 80-reg pressure
// (the LUT body holds 48). LUT computed per half-block (trivial).
// ---------------------------------------------------------------------------
__global__ __launch_bounds__(128, 10) void roi_kernel(
    const float* __restrict__ rois,
    const int*   __restrict__ bids,
    float*       __restrict__ out)
{
    extern __shared__ __half s_out[];   // [128][49] fp16
    __shared__ float s_w4[8][8][4];     // [i][j][w00,w01,w10,w11], 1KB
    __shared__ int   s_ws[8], s_hs[8];

    const int bx   = blockIdx.x;
    const int r    = bx >> 1;
    const int half = bx & 1;
    const int t    = threadIdx.x;
    const int p    = t & 63;           // pair index within half (channels 2p,2p+1)
    const int g    = t >> 6;           // warps 0-1: g=0, warps 2-3: g=1

    if (t < 64) {
        const int i = t >> 3;          // h-sample index
        const int j = t & 7;           // w-sample index
        float x1 = rois[r*4 + 0] * 0.0625f;
        float x2 = rois[r*4 + 2] * 0.0625f;
        float y1 = rois[r*4 + 1] * 0.0625f;
        float y2 = rois[r*4 + 3] * 0.0625f;
        float bw = fmaxf(x2 - x1 + 1.0f, 0.0f) * (1.0f / 7.0f);
        float bh = fmaxf(y2 - y1 + 1.0f, 0.0f) * (1.0f / 7.0f);
        float w  = x1 + (float)j * bw;
        float h  = y1 + (float)i * bh;
        float wm = (w >= 0.0f && w < (float)FW) ? 1.0f : 0.0f;
        float hm = (h >= 0.0f && h < (float)FH) ? 1.0f : 0.0f;
        float wsf = fminf(fmaxf(floorf(w), 0.0f), (float)(FW - 2));
        float hsf = fminf(fmaxf(floorf(h), 0.0f), (float)(FH - 2));
        float wf = w - wsf;
        float hf = h - hsf;
        float m  = hm * wm * 0.25f;            // mask + pool factor folded
        s_w4[i][j][0] = (1.0f - hf) * (1.0f - wf) * m;
        s_w4[i][j][1] = (1.0f - hf) * wf * m;
        s_w4[i][j][2] = hf * (1.0f - wf) * m;
        s_w4[i][j][3] = hf * wf * m;
        if (i == 0) s_ws[j] = (int)wsf * CCH;  // pre-scaled column offset
        if (j == 0) s_hs[i] = (int)hsf;
    }
    __syncthreads();

    const int b = bids[r];
    const __half* fbase = g_nhwc_h + (size_t)b * HW * CCH + half * HALF_CH + 2 * p;

    if (g == 0)
        process_rows_h2<5>(0, fbase, 2*p, s_ws, s_hs, s_w4, s_out);
    else
        process_rows_h2<4>(4, fbase, 2*p, s_ws, s_hs, s_w4, s_out);

    __syncthreads();

    // Coalesced flush: 4 halfs (8B-aligned) -> float4 store; this half's
    // output region is linear in global memory.
    float4* op = (float4*)(out + (size_t)r * OUT_PER_ROI + half * HALF_OUT);
    for (int m = t; m < HALF_OUT / 4; m += 128) {
        const half2* hp = (const half2*)(s_out + 4 * m);
        float2 lo = __half22float2(hp[0]);
        float2 hi = __half22float2(hp[1]);
        op[m] = make_float4(lo.x, lo.y, hi.x, hi.y);
    }
}

// ---------------------------------------------------------------------------
extern "C" void kernel_launch(void* const* d_in, const int* in_sizes, int n_in,
                              void* d_out, int out_size) {
    const float* features = (const float*)d_in[0];
    const float* rois     = (const float*)d_in[1];
    const int*   bids     = (const int*)d_in[2];
    float*       out      = (float*)d_out;

    dim3 tgrid(HW / 32, CCH / 128, NBATCH);   // (475, 2, 4) = 3800 blocks
    transpose_kernel<<<tgrid, dim3(32, 8)>>>(features);

    cudaFuncSetAttribute(roi_kernel,
                         cudaFuncAttributeMaxDynamicSharedMemorySize,
                         SMEM_BYTES);
    roi_kernel<<<NROI * 2, 128, SMEM_BYTES>>>(rois, bids, out);
}